// round 8
// baseline (speedup 1.0000x reference)
#include <cuda_runtime.h>
#include <cstdint>
#include <cstddef>

// ---- problem constants (from reference) ----
static constexpr int   BB = 4, HH = 400, WW = 400;
static constexpr float PCR0 = -80.0f, PCR1 = -80.0f;
static constexpr float BEVc = 0.4f;
static constexpr float ZC   = -1.0f;          // 0.5*(-5+3)
static constexpr float EPSBN = 1e-3f;
static constexpr int   NMAX = 1200000;
static constexpr int   CH = 64;
static constexpr int   K1 = 35;               // 32 features + 3 rel coords
static constexpr int   TBL = BB * HH * WW;
static constexpr int   TP  = 128;             // points per GEMM tile
static constexpr int   NSLOT = 8;

// ---- scratch (device globals: no allocation allowed) ----
__device__ int    g_table[TBL];
__device__ int    g_setidx[NMAX];
__device__ float  g_h[(size_t)CH * NMAX];     // SoA [channel][point]; reused in-place
__device__ double g_sum[2][CH][NSLOT];
__device__ double g_sq[2][CH][NSLOT];
__device__ float  g_ab[2][2][CH];             // [layer][a|b][ch]
__device__ float2 g_w1d[K1][CH];              // duplicated weights {w,w}
__device__ float2 g_w2d[CH][CH];

// ---- packed f32x2 helpers ----
__device__ __forceinline__ void fma2(unsigned long long& d, unsigned long long a,
                                     unsigned long long b) {
    asm("fma.rn.f32x2 %0, %1, %2, %0;" : "+l"(d) : "l"(a), "l"(b));
}
__device__ __forceinline__ void upk(unsigned long long v, float& lo, float& hi) {
    asm("mov.b64 {%0, %1}, %2;" : "=f"(lo), "=f"(hi) : "l"(v));
}
__device__ __forceinline__ float warp_sum(float v) {
    v += __shfl_xor_sync(0xffffffffu, v, 16);
    v += __shfl_xor_sync(0xffffffffu, v, 8);
    v += __shfl_xor_sync(0xffffffffu, v, 4);
    v += __shfl_xor_sync(0xffffffffu, v, 2);
    v += __shfl_xor_sync(0xffffffffu, v, 1);
    return v;
}

// ---------------------------------------------------------------------------
// Init kernels (pure kernels)
// ---------------------------------------------------------------------------
__global__ void k_init_out(float* __restrict__ out, int out_size) {
    int stride = gridDim.x * blockDim.x;
    for (int i = blockIdx.x * blockDim.x + threadIdx.x; i < out_size; i += stride)
        out[i] = 0.0f;
}
__global__ void k_init_tbl(const float* __restrict__ w1, const float* __restrict__ w2) {
    int stride = gridDim.x * blockDim.x;
    int t0 = blockIdx.x * blockDim.x + threadIdx.x;
    for (int i = t0; i < TBL; i += stride) g_table[i] = -1;
    double* s = &g_sum[0][0][0];
    for (int i = t0; i < 2 * CH * NSLOT; i += stride) s[i] = 0.0;
    double* q = &g_sq[0][0][0];
    for (int i = t0; i < 2 * CH * NSLOT; i += stride) q[i] = 0.0;
    // duplicated weight tables {w,w} for packed-f32x2 GEMM operands
    for (int i = t0; i < K1 * CH; i += stride) {
        int k = i / CH, c = i % CH;
        float w = w1[c * K1 + k];
        g_w1d[k][c] = make_float2(w, w);
    }
    for (int i = t0; i < CH * CH; i += stride) {
        int k = i / CH, c = i % CH;
        float w = w2[c * CH + k];
        g_w2d[k][c] = make_float2(w, w);
    }
}

// ---------------------------------------------------------------------------
// Pillar hash table: last-write-wins == highest pillar index wins
// ---------------------------------------------------------------------------
__global__ void k_build_table(const int* __restrict__ pind, int M) {
    int t = blockIdx.x * blockDim.x + threadIdx.x;
    if (t < M) {
        int b = pind[3 * t + 0];
        int y = pind[3 * t + 1];
        int x = pind[3 * t + 2];
        atomicMax(&g_table[(b * HH + y) * WW + x], t);
    }
}

// ---------------------------------------------------------------------------
// Shared GEMM epilogue: stats (sum, sumsq over points) + SoA store of outputs.
// acc layout: acc[c][0]={p0,p1}, acc[c][1]={p2,p3} for channel crow*8+c.
// OOB points have acc==0 (staged zeros) -> contribute 0 to stats, stores guarded.
// ---------------------------------------------------------------------------
__device__ __forceinline__ void gemm_epilogue(
    unsigned long long (&acc)[8][2], int n, int p0, int pcol, int crow,
    float* ssum, float* ssq, int layer, int slot)
{
    int pp = p0 + pcol * 4;
    bool full = ((n & 3) == 0) && (pp + 4 <= n);
    #pragma unroll
    for (int c = 0; c < 8; c++) {
        float v0, v1, v2, v3;
        upk(acc[c][0], v0, v1);
        upk(acc[c][1], v2, v3);
        float s = (v0 + v1) + (v2 + v3);
        float q = fmaf(v0, v0, fmaf(v1, v1, fmaf(v2, v2, v3 * v3)));
        s = warp_sum(s);
        q = warp_sum(q);
        int ch = crow * 8 + c;
        if (pcol == 0) { ssum[ch] = s; ssq[ch] = q; }
        float* dst = &g_h[(size_t)ch * n + pp];
        if (full) {
            *(float4*)dst = make_float4(v0, v1, v2, v3);
        } else {
            if (pp + 0 < n) dst[0] = v0;
            if (pp + 1 < n) dst[1] = v1;
            if (pp + 2 < n) dst[2] = v2;
            if (pp + 3 < n) dst[3] = v3;
        }
    }
    __syncthreads();
    if (threadIdx.x < CH) {
        atomicAdd(&g_sum[layer][threadIdx.x][slot], (double)ssum[threadIdx.x]);
        atomicAdd(&g_sq[layer][threadIdx.x][slot], (double)ssq[threadIdx.x]);
    }
}

// ---------------------------------------------------------------------------
// Pass 1: group features + h1_pre = g @ w1^T  (f32x2 GEMM), BN1 stats.
// A in smem; W via warp-uniform __ldg from duplicated global table (keeps the
// smem crossbar for A only). 8 channels x 4 points per thread, 3 CTAs/SM.
// ---------------------------------------------------------------------------
__global__ __launch_bounds__(256, 3) void k_pass1(
    const float* __restrict__ xyz, const int* __restrict__ bidx,
    const float* __restrict__ pf, int n)
{
    __shared__ __align__(16) float Ast[K1][132];     // [k][pt], padded
    __shared__ float ssum[CH], ssq[CH];
    int tid = threadIdx.x;
    int p0 = blockIdx.x * TP;

    // stage point features (transpose [pt][32] -> A[k][pt]), coalesced LDG.128
    const float4* pf4 = (const float4*)pf;
    #pragma unroll
    for (int i = 0; i < 4; i++) {
        int idx = tid + 256 * i;              // 0..1023
        int pt = idx >> 3, kq = idx & 7;
        int gp = p0 + pt;
        float4 v = make_float4(0.f, 0.f, 0.f, 0.f);
        if (gp < n) v = pf4[(size_t)gp * 8 + kq];
        Ast[kq * 4 + 0][pt] = v.x;
        Ast[kq * 4 + 1][pt] = v.y;
        Ast[kq * 4 + 2][pt] = v.z;
        Ast[kq * 4 + 3][pt] = v.w;
    }
    // rel coords + pillar lookup (threads 0..127, one point each)
    if (tid < TP) {
        int gp = p0 + tid;
        float rx = 0.f, ry = 0.f, rz = 0.f;
        if (gp < n) {
            float x = xyz[3 * gp + 0], y = xyz[3 * gp + 1], z = xyz[3 * gp + 2];
            int xi = (int)floorf(__fdiv_rn(x - PCR0, BEVc));
            int yi = (int)floorf(__fdiv_rn(y - PCR1, BEVc));
            xi = min(max(xi, 0), WW - 1);
            yi = min(max(yi, 0), HH - 1);
            g_setidx[gp] = g_table[(bidx[gp] * HH + yi) * WW + xi];
            rx = x - (PCR0 + ((float)xi + 0.5f) * BEVc);
            ry = y - (PCR1 + ((float)yi + 0.5f) * BEVc);
            rz = z - ZC;
        }
        Ast[32][tid] = rx;
        Ast[33][tid] = ry;
        Ast[34][tid] = rz;
    }
    __syncthreads();

    int pcol = tid & 31, crow = tid >> 5;
    unsigned long long acc[8][2];
    #pragma unroll
    for (int c = 0; c < 8; c++) { acc[c][0] = 0ull; acc[c][1] = 0ull; }

    #pragma unroll
    for (int k = 0; k < K1; k++) {
        ulonglong2 a = *(const ulonglong2*)&Ast[k][pcol * 4];
        const ulonglong2* wp = (const ulonglong2*)&g_w1d[k][crow * 8];
        #pragma unroll
        for (int j = 0; j < 4; j++) {
            ulonglong2 w = __ldg(wp + j);
            fma2(acc[2 * j + 0][0], a.x, w.x);
            fma2(acc[2 * j + 0][1], a.y, w.x);
            fma2(acc[2 * j + 1][0], a.x, w.y);
            fma2(acc[2 * j + 1][1], a.y, w.y);
        }
    }
    gemm_epilogue(acc, n, p0, pcol, crow, ssum, ssq, 0, blockIdx.x & (NSLOT - 1));
}

// ---------------------------------------------------------------------------
// Finalize BN stats (reduce slots, double) -> affine a,b
// ---------------------------------------------------------------------------
__global__ void k_fin(int layer, float invn,
                      const float* __restrict__ gamma, const float* __restrict__ beta)
{
    int c = threadIdx.x;
    if (c < CH) {
        double S = 0.0, Q = 0.0;
        #pragma unroll
        for (int s = 0; s < NSLOT; s++) { S += g_sum[layer][c][s]; Q += g_sq[layer][c][s]; }
        float mu  = (float)(S * (double)invn);
        float var = (float)(Q * (double)invn) - mu * mu;
        float a = rsqrtf(var + EPSBN) * gamma[c];
        g_ab[layer][0][c] = a;
        g_ab[layer][1][c] = fmaf(-mu, a, beta[c]);
    }
}

// ---------------------------------------------------------------------------
// Pass 2: h1 = relu(bn1(h1_pre)); h2_pre = h1 @ w2^T (f32x2 GEMM, K chunked),
// BN2 stats; overwrites g_h in place (tile fully read before write).
// W via warp-uniform __ldg.
// ---------------------------------------------------------------------------
__global__ __launch_bounds__(256, 3) void k_pass2(int n)
{
    __shared__ __align__(16) float Ast[32][132];
    __shared__ float sa[CH], sb[CH];
    __shared__ float ssum[CH], ssq[CH];
    int tid = threadIdx.x;
    int p0 = blockIdx.x * TP;
    int lane = tid & 31, wid = tid >> 5;

    if (tid < CH) { sa[tid] = g_ab[0][0][tid]; sb[tid] = g_ab[0][1][tid]; }

    unsigned long long acc[8][2];
    #pragma unroll
    for (int c = 0; c < 8; c++) { acc[c][0] = 0ull; acc[c][1] = 0ull; }

    bool aligned = ((n & 3) == 0);

    for (int chunk = 0; chunk < 2; chunk++) {
        __syncthreads();   // sa ready (chunk 0) / previous GEMM done reading smem
        // stage A: h1 = relu(bn1(h1_pre)) for rows k=chunk*32..+31
        #pragma unroll
        for (int i = 0; i < 4; i++) {
            int r = wid + 8 * i;               // 0..31
            int kc = chunk * 32 + r;
            int gp = p0 + lane * 4;
            const float* src = &g_h[(size_t)kc * n + gp];
            float4 v = make_float4(0.f, 0.f, 0.f, 0.f);
            if (aligned && gp + 4 <= n) {
                v = *(const float4*)src;
            } else {
                if (gp + 0 < n) v.x = src[0];
                if (gp + 1 < n) v.y = src[1];
                if (gp + 2 < n) v.z = src[2];
                if (gp + 3 < n) v.w = src[3];
            }
            float a = sa[kc], b = sb[kc];
            float4 h;
            h.x = (gp + 0 < n) ? fmaxf(fmaf(v.x, a, b), 0.f) : 0.f;
            h.y = (gp + 1 < n) ? fmaxf(fmaf(v.y, a, b), 0.f) : 0.f;
            h.z = (gp + 2 < n) ? fmaxf(fmaf(v.z, a, b), 0.f) : 0.f;
            h.w = (gp + 3 < n) ? fmaxf(fmaf(v.w, a, b), 0.f) : 0.f;
            *(float4*)&Ast[r][lane * 4] = h;
        }
        __syncthreads();

        #pragma unroll
        for (int k = 0; k < 32; k++) {
            ulonglong2 a = *(const ulonglong2*)&Ast[k][lane * 4];
            const ulonglong2* wp = (const ulonglong2*)&g_w2d[chunk * 32 + k][wid * 8];
            #pragma unroll
            for (int j = 0; j < 4; j++) {
                ulonglong2 w = __ldg(wp + j);
                fma2(acc[2 * j + 0][0], a.x, w.x);
                fma2(acc[2 * j + 0][1], a.y, w.x);
                fma2(acc[2 * j + 1][0], a.x, w.y);
                fma2(acc[2 * j + 1][1], a.y, w.y);
            }
        }
    }
    __syncthreads();
    gemm_epilogue(acc, n, p0, lane, wid, ssum, ssq, 1, blockIdx.x & (NSLOT - 1));
}

// ---------------------------------------------------------------------------
// Pass 3: y = relu(bn2(h2_pre)); scatter-max into pillars.
// Post-ReLU values >= 0; int-bit atomicMax on zeroed output == segment_max
// with empty -> 0.  v<=0 skips the atomic.
// ---------------------------------------------------------------------------
__global__ __launch_bounds__(256) void k_pass3(int n, int* __restrict__ out)
{
    __shared__ float sa[CH], sb[CH];
    if (threadIdx.x < CH) {
        sa[threadIdx.x] = g_ab[1][0][threadIdx.x];
        sb[threadIdx.x] = g_ab[1][1][threadIdx.x];
    }
    __syncthreads();

    int base = (blockIdx.x * 256 + threadIdx.x) * 4;
    if (base >= n) return;

    if (((n & 3) == 0) && base + 4 <= n) {
        int4 si = *(const int4*)&g_setidx[base];
        #pragma unroll 8
        for (int c = 0; c < CH; c++) {
            float4 v = *(const float4*)&g_h[(size_t)c * n + base];
            float a = sa[c], b = sb[c];
            float x0 = fmaf(v.x, a, b);
            float x1 = fmaf(v.y, a, b);
            float x2 = fmaf(v.z, a, b);
            float x3 = fmaf(v.w, a, b);
            if (x0 > 0.f && si.x >= 0) atomicMax(&out[si.x * CH + c], __float_as_int(x0));
            if (x1 > 0.f && si.y >= 0) atomicMax(&out[si.y * CH + c], __float_as_int(x1));
            if (x2 > 0.f && si.z >= 0) atomicMax(&out[si.z * CH + c], __float_as_int(x2));
            if (x3 > 0.f && si.w >= 0) atomicMax(&out[si.w * CH + c], __float_as_int(x3));
        }
    } else {
        for (int j = 0; j < 4 && base + j < n; j++) {
            int si = g_setidx[base + j];
            if (si < 0) continue;
            for (int c = 0; c < CH; c++) {
                float x = fmaf(g_h[(size_t)c * n + base + j], sa[c], sb[c]);
                if (x > 0.f) atomicMax(&out[si * CH + c], __float_as_int(x));
            }
        }
    }
}

// ---------------------------------------------------------------------------
extern "C" void kernel_launch(void* const* d_in, const int* in_sizes, int n_in,
                              void* d_out, int out_size)
{
    const float* xyz    = (const float*)d_in[0];
    const int*   bidx   = (const int*)  d_in[1];
    const float* pf     = (const float*)d_in[2];
    const int*   pind   = (const int*)  d_in[3];
    const float* w1     = (const float*)d_in[4];
    const float* gamma1 = (const float*)d_in[5];
    const float* beta1  = (const float*)d_in[6];
    const float* w2     = (const float*)d_in[7];
    const float* gamma2 = (const float*)d_in[8];
    const float* beta2  = (const float*)d_in[9];

    int n = in_sizes[0] / 3;      // points
    int M = in_sizes[3] / 3;      // pillars

    int nbt = (n + TP - 1) / TP;
    float invn = 1.0f / (float)n;

    k_init_out<<<512, 256>>>((float*)d_out, out_size);                 // #1
    k_init_tbl<<<512, 256>>>(w1, w2);                                  // #2
    k_build_table<<<(M + 255) / 256, 256>>>(pind, M);                  // #3
    k_pass1<<<nbt, 256>>>(xyz, bidx, pf, n);                           // #4
    k_fin<<<1, 64>>>(0, invn, gamma1, beta1);                          // #5
    k_pass2<<<nbt, 256>>>(n);                                          // #6
    k_fin<<<1, 64>>>(1, invn, gamma2, beta2);                          // #7
    k_pass3<<<(n + 1023) / 1024, 256>>>(n, (int*)d_out);               // #8
}

// round 9
// speedup vs baseline: 1.3484x; 1.3484x over previous
#include <cuda_runtime.h>
#include <cstdint>
#include <cstddef>

// ---- problem constants (from reference) ----
static constexpr int   BB = 4, HH = 400, WW = 400;
static constexpr float PCR0 = -80.0f, PCR1 = -80.0f;
static constexpr float BEVc = 0.4f;
static constexpr float ZC   = -1.0f;          // 0.5*(-5+3)
static constexpr float EPSBN = 1e-3f;
static constexpr int   NMAX = 1200000;
static constexpr int   CH = 64;
static constexpr int   K1 = 35;               // 32 features + 3 rel coords
static constexpr int   TBL = BB * HH * WW;
static constexpr int   TP  = 192;             // points per GEMM tile (8ch x 6pt / thread)
static constexpr int   APAD = 196;            // A row stride (16B aligned, 2-way max on stage)
static constexpr int   NSLOT = 8;

// ---- scratch (device globals: no allocation allowed) ----
__device__ int    g_table[TBL];
__device__ int    g_setidx[NMAX];
__device__ float  g_h[(size_t)CH * NMAX];     // SoA [channel][point]; reused in-place
__device__ double g_sum[2][CH][NSLOT];
__device__ double g_sq[2][CH][NSLOT];
__device__ float  g_ab[2][2][CH];             // [layer][a|b][ch]

// ---- packed f32x2 helpers ----
__device__ __forceinline__ void fma2(unsigned long long& d, unsigned long long a,
                                     unsigned long long b) {
    asm("fma.rn.f32x2 %0, %1, %2, %0;" : "+l"(d) : "l"(a), "l"(b));
}
__device__ __forceinline__ void upk(unsigned long long v, float& lo, float& hi) {
    asm("mov.b64 {%0, %1}, %2;" : "=f"(lo), "=f"(hi) : "l"(v));
}
__device__ __forceinline__ float warp_sum(float v) {
    v += __shfl_xor_sync(0xffffffffu, v, 16);
    v += __shfl_xor_sync(0xffffffffu, v, 8);
    v += __shfl_xor_sync(0xffffffffu, v, 4);
    v += __shfl_xor_sync(0xffffffffu, v, 2);
    v += __shfl_xor_sync(0xffffffffu, v, 1);
    return v;
}

// ---------------------------------------------------------------------------
// Init kernels (pure kernels)
// ---------------------------------------------------------------------------
__global__ void k_init_out(float* __restrict__ out, int out_size) {
    int stride = gridDim.x * blockDim.x;
    for (int i = blockIdx.x * blockDim.x + threadIdx.x; i < out_size; i += stride)
        out[i] = 0.0f;
}
__global__ void k_init_tbl() {
    int stride = gridDim.x * blockDim.x;
    int t0 = blockIdx.x * blockDim.x + threadIdx.x;
    for (int i = t0; i < TBL; i += stride) g_table[i] = -1;
    double* s = &g_sum[0][0][0];
    for (int i = t0; i < 2 * CH * NSLOT; i += stride) s[i] = 0.0;
    double* q = &g_sq[0][0][0];
    for (int i = t0; i < 2 * CH * NSLOT; i += stride) q[i] = 0.0;
}

// ---------------------------------------------------------------------------
// Pillar hash table: last-write-wins == highest pillar index wins
// ---------------------------------------------------------------------------
__global__ void k_build_table(const int* __restrict__ pind, int M) {
    int t = blockIdx.x * blockDim.x + threadIdx.x;
    if (t < M) {
        int b = pind[3 * t + 0];
        int y = pind[3 * t + 1];
        int x = pind[3 * t + 2];
        atomicMax(&g_table[(b * HH + y) * WW + x], t);
    }
}

// ---------------------------------------------------------------------------
// Shared GEMM epilogue for the 8ch x 6pt tile.
// acc[c][0..1] -> points pp0..pp0+3 ; acc[c][2] -> points pp1, pp1+1.
// OOB points hold zeros -> contribute 0 to stats; stores guarded.
// ---------------------------------------------------------------------------
__device__ __forceinline__ void gemm_epilogue6(
    unsigned long long (&acc)[8][3], int n, int p0, int lane, int wid,
    float* ssum, float* ssq, int layer, int slot)
{
    int pp0 = p0 + lane * 4;
    int pp1 = p0 + 128 + lane * 2;
    bool full0 = ((n & 3) == 0) && (pp0 + 4 <= n);
    bool full1 = ((n & 1) == 0) && (pp1 + 2 <= n);
    #pragma unroll
    for (int c = 0; c < 8; c++) {
        float v0, v1, v2, v3, v4, v5;
        upk(acc[c][0], v0, v1);
        upk(acc[c][1], v2, v3);
        upk(acc[c][2], v4, v5);
        float s = ((v0 + v1) + (v2 + v3)) + (v4 + v5);
        float q = fmaf(v0, v0, fmaf(v1, v1, fmaf(v2, v2, v3 * v3)))
                + fmaf(v4, v4, v5 * v5);
        s = warp_sum(s);
        q = warp_sum(q);
        int ch = wid * 8 + c;
        if (lane == 0) { ssum[ch] = s; ssq[ch] = q; }
        float* dst0 = &g_h[(size_t)ch * n + pp0];
        float* dst1 = &g_h[(size_t)ch * n + pp1];
        if (full0) {
            *(float4*)dst0 = make_float4(v0, v1, v2, v3);
        } else {
            if (pp0 + 0 < n) dst0[0] = v0;
            if (pp0 + 1 < n) dst0[1] = v1;
            if (pp0 + 2 < n) dst0[2] = v2;
            if (pp0 + 3 < n) dst0[3] = v3;
        }
        if (full1) {
            *(float2*)dst1 = make_float2(v4, v5);
        } else {
            if (pp1 + 0 < n) dst1[0] = v4;
            if (pp1 + 1 < n) dst1[1] = v5;
        }
    }
    __syncthreads();
    if (threadIdx.x < CH) {
        atomicAdd(&g_sum[layer][threadIdx.x][slot], (double)ssum[threadIdx.x]);
        atomicAdd(&g_sq[layer][threadIdx.x][slot], (double)ssq[threadIdx.x]);
    }
}

// ---------------------------------------------------------------------------
// Pass 1: group features + h1_pre = g @ w1^T  (f32x2 GEMM), BN1 stats.
// A and duplicated W both in smem (broadcast LDS for W). 8ch x 6pt per
// thread; 3 CTAs/SM.
// ---------------------------------------------------------------------------
__global__ __launch_bounds__(256, 3) void k_pass1(
    const float* __restrict__ xyz, const int* __restrict__ bidx,
    const float* __restrict__ pf, const float* __restrict__ w1, int n)
{
    __shared__ __align__(16) float  Ast[K1][APAD];   // 27.4 KB
    __shared__ __align__(16) float2 Wd[K1][CH];      // 17.9 KB, {w,w}
    __shared__ float ssum[CH], ssq[CH];
    int tid = threadIdx.x;
    int lane = tid & 31, wid = tid >> 5;
    int p0 = blockIdx.x * TP;

    // stage duplicated weights
    for (int idx = tid; idx < K1 * CH; idx += 256) {
        int k = idx >> 6, c = idx & 63;
        float w = w1[c * K1 + k];
        Wd[k][c] = make_float2(w, w);
    }
    // stage point features (transpose [pt][32] -> A[k][pt]), coalesced LDG.128
    const float4* pf4 = (const float4*)pf;
    #pragma unroll
    for (int i = 0; i < 6; i++) {
        int idx = tid + 256 * i;              // 0..1535
        int pt = idx >> 3, kq = idx & 7;
        int gp = p0 + pt;
        float4 v = make_float4(0.f, 0.f, 0.f, 0.f);
        if (gp < n) v = pf4[(size_t)gp * 8 + kq];
        Ast[kq * 4 + 0][pt] = v.x;
        Ast[kq * 4 + 1][pt] = v.y;
        Ast[kq * 4 + 2][pt] = v.z;
        Ast[kq * 4 + 3][pt] = v.w;
    }
    // rel coords + pillar lookup (threads 0..191, one point each)
    if (tid < TP) {
        int gp = p0 + tid;
        float rx = 0.f, ry = 0.f, rz = 0.f;
        if (gp < n) {
            float x = xyz[3 * gp + 0], y = xyz[3 * gp + 1], z = xyz[3 * gp + 2];
            int xi = (int)floorf(__fdiv_rn(x - PCR0, BEVc));
            int yi = (int)floorf(__fdiv_rn(y - PCR1, BEVc));
            xi = min(max(xi, 0), WW - 1);
            yi = min(max(yi, 0), HH - 1);
            g_setidx[gp] = g_table[(bidx[gp] * HH + yi) * WW + xi];
            rx = x - (PCR0 + ((float)xi + 0.5f) * BEVc);
            ry = y - (PCR1 + ((float)yi + 0.5f) * BEVc);
            rz = z - ZC;
        }
        Ast[32][tid] = rx;
        Ast[33][tid] = ry;
        Ast[34][tid] = rz;
    }
    __syncthreads();

    unsigned long long acc[8][3];
    #pragma unroll
    for (int c = 0; c < 8; c++) { acc[c][0] = 0ull; acc[c][1] = 0ull; acc[c][2] = 0ull; }

    #pragma unroll
    for (int k = 0; k < K1; k++) {
        ulonglong2 a0 = *(const ulonglong2*)&Ast[k][lane * 4];
        unsigned long long a1 = *(const unsigned long long*)&Ast[k][128 + lane * 2];
        const ulonglong2* wp = (const ulonglong2*)&Wd[k][wid * 8];
        #pragma unroll
        for (int j = 0; j < 4; j++) {
            ulonglong2 w = wp[j];
            fma2(acc[2 * j + 0][0], a0.x, w.x);
            fma2(acc[2 * j + 0][1], a0.y, w.x);
            fma2(acc[2 * j + 0][2], a1,   w.x);
            fma2(acc[2 * j + 1][0], a0.x, w.y);
            fma2(acc[2 * j + 1][1], a0.y, w.y);
            fma2(acc[2 * j + 1][2], a1,   w.y);
        }
    }
    gemm_epilogue6(acc, n, p0, lane, wid, ssum, ssq, 0, blockIdx.x & (NSLOT - 1));
}

// ---------------------------------------------------------------------------
// Finalize BN stats (reduce slots, double) -> affine a,b
// ---------------------------------------------------------------------------
__global__ void k_fin(int layer, float invn,
                      const float* __restrict__ gamma, const float* __restrict__ beta)
{
    int c = threadIdx.x;
    if (c < CH) {
        double S = 0.0, Q = 0.0;
        #pragma unroll
        for (int s = 0; s < NSLOT; s++) { S += g_sum[layer][c][s]; Q += g_sq[layer][c][s]; }
        float mu  = (float)(S * (double)invn);
        float var = (float)(Q * (double)invn) - mu * mu;
        float a = rsqrtf(var + EPSBN) * gamma[c];
        g_ab[layer][0][c] = a;
        g_ab[layer][1][c] = fmaf(-mu, a, beta[c]);
    }
}

// ---------------------------------------------------------------------------
// Pass 2: h1 = relu(bn1(h1_pre)); h2_pre = h1 @ w2^T (f32x2 GEMM, K chunked
// 2x32), BN2 stats; overwrites g_h in place (tile fully read before write).
// ---------------------------------------------------------------------------
__global__ __launch_bounds__(256, 3) void k_pass2(const float* __restrict__ w2, int n)
{
    __shared__ __align__(16) float  Ast[32][APAD];   // 25.1 KB
    __shared__ __align__(16) float2 Wd[32][CH];      // 16.4 KB
    __shared__ float sa[CH], sb[CH];
    __shared__ float ssum[CH], ssq[CH];
    int tid = threadIdx.x;
    int lane = tid & 31, wid = tid >> 5;
    int p0 = blockIdx.x * TP;

    if (tid < CH) { sa[tid] = g_ab[0][0][tid]; sb[tid] = g_ab[0][1][tid]; }

    unsigned long long acc[8][3];
    #pragma unroll
    for (int c = 0; c < 8; c++) { acc[c][0] = 0ull; acc[c][1] = 0ull; acc[c][2] = 0ull; }

    bool a4 = ((n & 3) == 0);
    bool a2 = ((n & 1) == 0);

    for (int chunk = 0; chunk < 2; chunk++) {
        __syncthreads();   // sa ready (chunk 0) / previous GEMM done reading smem
        // stage duplicated weights for this K chunk
        for (int idx = tid; idx < 32 * CH; idx += 256) {
            int k = idx >> 6, c = idx & 63;
            float w = w2[c * CH + chunk * 32 + k];
            Wd[k][c] = make_float2(w, w);
        }
        // stage A: h1 = relu(bn1(h1_pre)); warp wid handles rows wid*4..+3
        #pragma unroll
        for (int rr = 0; rr < 4; rr++) {
            int r = wid * 4 + rr;
            int kc = chunk * 32 + r;
            float a = sa[kc], b = sb[kc];
            // first 128 points: float4
            {
                int gp = p0 + lane * 4;
                const float* src = &g_h[(size_t)kc * n + gp];
                float4 v = make_float4(0.f, 0.f, 0.f, 0.f);
                if (a4 && gp + 4 <= n) {
                    v = *(const float4*)src;
                } else {
                    if (gp + 0 < n) v.x = src[0];
                    if (gp + 1 < n) v.y = src[1];
                    if (gp + 2 < n) v.z = src[2];
                    if (gp + 3 < n) v.w = src[3];
                }
                float4 h;
                h.x = (gp + 0 < n) ? fmaxf(fmaf(v.x, a, b), 0.f) : 0.f;
                h.y = (gp + 1 < n) ? fmaxf(fmaf(v.y, a, b), 0.f) : 0.f;
                h.z = (gp + 2 < n) ? fmaxf(fmaf(v.z, a, b), 0.f) : 0.f;
                h.w = (gp + 3 < n) ? fmaxf(fmaf(v.w, a, b), 0.f) : 0.f;
                *(float4*)&Ast[r][lane * 4] = h;
            }
            // points 128..191: float2
            {
                int gp = p0 + 128 + lane * 2;
                const float* src = &g_h[(size_t)kc * n + gp];
                float2 v = make_float2(0.f, 0.f);
                if (a2 && gp + 2 <= n) {
                    v = *(const float2*)src;
                } else {
                    if (gp + 0 < n) v.x = src[0];
                    if (gp + 1 < n) v.y = src[1];
                }
                float2 h;
                h.x = (gp + 0 < n) ? fmaxf(fmaf(v.x, a, b), 0.f) : 0.f;
                h.y = (gp + 1 < n) ? fmaxf(fmaf(v.y, a, b), 0.f) : 0.f;
                *(float2*)&Ast[r][128 + lane * 2] = h;
            }
        }
        __syncthreads();

        #pragma unroll
        for (int k = 0; k < 32; k++) {
            ulonglong2 a0 = *(const ulonglong2*)&Ast[k][lane * 4];
            unsigned long long a1 = *(const unsigned long long*)&Ast[k][128 + lane * 2];
            const ulonglong2* wp = (const ulonglong2*)&Wd[k][wid * 8];
            #pragma unroll
            for (int j = 0; j < 4; j++) {
                ulonglong2 w = wp[j];
                fma2(acc[2 * j + 0][0], a0.x, w.x);
                fma2(acc[2 * j + 0][1], a0.y, w.x);
                fma2(acc[2 * j + 0][2], a1,   w.x);
                fma2(acc[2 * j + 1][0], a0.x, w.y);
                fma2(acc[2 * j + 1][1], a0.y, w.y);
                fma2(acc[2 * j + 1][2], a1,   w.y);
            }
        }
    }
    __syncthreads();
    gemm_epilogue6(acc, n, p0, lane, wid, ssum, ssq, 1, blockIdx.x & (NSLOT - 1));
}

// ---------------------------------------------------------------------------
// Pass 3: y = relu(bn2(h2_pre)); scatter-max into pillars.
// Post-ReLU values >= 0; int-bit atomicMax on zeroed output == segment_max
// with empty -> 0.  v<=0 skips the atomic.
// ---------------------------------------------------------------------------
__global__ __launch_bounds__(256) void k_pass3(int n, int* __restrict__ out)
{
    __shared__ float sa[CH], sb[CH];
    if (threadIdx.x < CH) {
        sa[threadIdx.x] = g_ab[1][0][threadIdx.x];
        sb[threadIdx.x] = g_ab[1][1][threadIdx.x];
    }
    __syncthreads();

    int base = (blockIdx.x * 256 + threadIdx.x) * 4;
    if (base >= n) return;

    if (((n & 3) == 0) && base + 4 <= n) {
        int4 si = *(const int4*)&g_setidx[base];
        #pragma unroll 8
        for (int c = 0; c < CH; c++) {
            float4 v = *(const float4*)&g_h[(size_t)c * n + base];
            float a = sa[c], b = sb[c];
            float x0 = fmaf(v.x, a, b);
            float x1 = fmaf(v.y, a, b);
            float x2 = fmaf(v.z, a, b);
            float x3 = fmaf(v.w, a, b);
            if (x0 > 0.f && si.x >= 0) atomicMax(&out[si.x * CH + c], __float_as_int(x0));
            if (x1 > 0.f && si.y >= 0) atomicMax(&out[si.y * CH + c], __float_as_int(x1));
            if (x2 > 0.f && si.z >= 0) atomicMax(&out[si.z * CH + c], __float_as_int(x2));
            if (x3 > 0.f && si.w >= 0) atomicMax(&out[si.w * CH + c], __float_as_int(x3));
        }
    } else {
        for (int j = 0; j < 4 && base + j < n; j++) {
            int si = g_setidx[base + j];
            if (si < 0) continue;
            for (int c = 0; c < CH; c++) {
                float x = fmaf(g_h[(size_t)c * n + base + j], sa[c], sb[c]);
                if (x > 0.f) atomicMax(&out[si * CH + c], __float_as_int(x));
            }
        }
    }
}

// ---------------------------------------------------------------------------
extern "C" void kernel_launch(void* const* d_in, const int* in_sizes, int n_in,
                              void* d_out, int out_size)
{
    const float* xyz    = (const float*)d_in[0];
    const int*   bidx   = (const int*)  d_in[1];
    const float* pf     = (const float*)d_in[2];
    const int*   pind   = (const int*)  d_in[3];
    const float* w1     = (const float*)d_in[4];
    const float* gamma1 = (const float*)d_in[5];
    const float* beta1  = (const float*)d_in[6];
    const float* w2     = (const float*)d_in[7];
    const float* gamma2 = (const float*)d_in[8];
    const float* beta2  = (const float*)d_in[9];

    int n = in_sizes[0] / 3;      // points
    int M = in_sizes[3] / 3;      // pillars

    int nbt = (n + TP - 1) / TP;
    float invn = 1.0f / (float)n;

    k_init_out<<<512, 256>>>((float*)d_out, out_size);                 // #1
    k_init_tbl<<<512, 256>>>();                                        // #2
    k_build_table<<<(M + 255) / 256, 256>>>(pind, M);                  // #3
    k_pass1<<<nbt, 256>>>(xyz, bidx, pf, w1, n);                       // #4
    k_fin<<<1, 64>>>(0, invn, gamma1, beta1);                          // #5
    k_pass2<<<nbt, 256>>>(w2, n);                                      // #6
    k_fin<<<1, 64>>>(1, invn, gamma2, beta2);                          // #7
    k_pass3<<<(n + 1023) / 1024, 256>>>(n, (int*)d_out);               // #8
}